// round 17
// baseline (speedup 1.0000x reference)
#include <cuda_runtime.h>
#include <cuda_fp16.h>
#include <math.h>
#include <stdint.h>

#define SLEN 2048
#define BATCH 64
#define DIN 512
#define DSRC 512
#define DAL 512
#define NTOK (SLEN * BATCH)       // 131072
#define CTX_ELEMS (BATCH * DSRC)  // 32768

// ---------------------------------------------------------------------------
// Scratch (__device__ globals; no cudaMalloc allowed)
// ---------------------------------------------------------------------------
__device__ float g_q[BATCH * DAL];               // input@W1[:, :512]^T + b1
__device__ float g_part[4 * NTOK];               // per-n-tile partial scores [nt][b][s]
__device__ __half g_Af16[(size_t)NTOK * DSRC];   // src as fp16 (128MB)
__device__ __half g_Bf16[DAL * DSRC];            // W1[:, 512:] as fp16 (512KB)

// ---------------------------------------------------------------------------
// Helpers
// ---------------------------------------------------------------------------
#define SW128(o) ((o) ^ (((o) >> 3) & 0x70))

__device__ __forceinline__ uint32_t smem_u32(const void* p) {
    uint32_t a;
    asm("{ .reg .u64 t; cvta.to.shared.u64 t, %1; cvt.u32.u64 %0, t; }" : "=r"(a) : "l"(p));
    return a;
}
#define CP16(dst, src) \
    asm volatile("cp.async.cg.shared.global [%0], [%1], 16;" :: "r"(dst), "l"(src))
#define CP_COMMIT() asm volatile("cp.async.commit_group;" ::: "memory")
#define CP_WAIT1() asm volatile("cp.async.wait_group 1;" ::: "memory")
#define CP_WAIT0() asm volatile("cp.async.wait_group 0;" ::: "memory")

__device__ __forceinline__ void ldsm4(uint32_t* r, uint32_t addr) {
    asm volatile("ldmatrix.sync.aligned.m8n8.x4.shared.b16 {%0,%1,%2,%3}, [%4];"
                 : "=r"(r[0]), "=r"(r[1]), "=r"(r[2]), "=r"(r[3]) : "r"(addr));
}
// D += A*B, fp16 m16n8k16, fp32 accum. a: 4 regs, b: 2 regs
__device__ __forceinline__ void mma_f16(float* d, const uint32_t* a,
                                        uint32_t b0, uint32_t b1) {
    asm volatile("mma.sync.aligned.m16n8k16.row.col.f32.f16.f16.f32 "
                 "{%0,%1,%2,%3}, {%4,%5,%6,%7}, {%8,%9}, {%0,%1,%2,%3};"
                 : "+f"(d[0]), "+f"(d[1]), "+f"(d[2]), "+f"(d[3])
                 : "r"(a[0]), "r"(a[1]), "r"(a[2]), "r"(a[3]), "r"(b0), "r"(b1));
}
// Single-MUFU tanh (sm_75+).
__device__ __forceinline__ float fast_tanh(float x) {
    float y;
    asm("tanh.approx.f32 %0, %1;" : "=f"(y) : "f"(x));
    return y;
}
__device__ __forceinline__ uint32_t h2_bits(__half2 h) {
    uint32_t u;
    memcpy(&u, &h, 4);
    return u;
}
__device__ __forceinline__ uint4 cvt8_f16(float4 v0, float4 v1) {
    uint4 o;
    o.x = h2_bits(__floats2half2_rn(v0.x, v0.y));
    o.y = h2_bits(__floats2half2_rn(v0.z, v0.w));
    o.z = h2_bits(__floats2half2_rn(v1.x, v1.y));
    o.w = h2_bits(__floats2half2_rn(v1.z, v1.w));
    return o;
}

// ---------------------------------------------------------------------------
// Fused pre-kernel: convA | k_q | convB | zero-ctx
// ---------------------------------------------------------------------------
#define PRE_A_BLOCKS 32768
#define PRE_Q_BLOCKS 4096
#define PRE_B_BLOCKS 128
#define PRE_Z_BLOCKS 32
#define PRE_TOTAL (PRE_A_BLOCKS + PRE_Q_BLOCKS + PRE_B_BLOCKS + PRE_Z_BLOCKS)

__global__ __launch_bounds__(256) void k_pre(const float* __restrict__ src,
                                             const float* __restrict__ inp,
                                             const float* __restrict__ W1,
                                             const float* __restrict__ b1,
                                             float* __restrict__ out) {
    const int bx = blockIdx.x;
    const int tid = threadIdx.x;
    if (bx < PRE_A_BLOCKS) {
        size_t u = (size_t)bx * 256 + tid;               // 8.39M units of 8 elems
        const float* p = src + u * 8;
        float4 v0 = *(const float4*)p;
        float4 v1 = *(const float4*)(p + 4);
        *(uint4*)((char*)g_Af16 + u * 16) = cvt8_f16(v0, v1);
    } else if (bx < PRE_A_BLOCKS + PRE_Q_BLOCKS) {
        int gw = (bx - PRE_A_BLOCKS) * 8 + (tid >> 5);
        int lane = tid & 31;
        int b = gw >> 9, a = gw & 511;
        const float* ip = inp + b * DIN;
        const float* wp = W1 + (size_t)a * (DIN + DSRC);
        float s = 0.f;
        #pragma unroll 4
        for (int k = lane; k < DIN; k += 32) s += ip[k] * wp[k];
        #pragma unroll
        for (int o = 16; o; o >>= 1) s += __shfl_xor_sync(0xFFFFFFFFu, s, o);
        if (lane == 0) g_q[b * DAL + a] = s + b1[a];
    } else if (bx < PRE_A_BLOCKS + PRE_Q_BLOCKS + PRE_B_BLOCKS) {
        int u = (bx - PRE_A_BLOCKS - PRE_Q_BLOCKS) * 256 + tid;  // 32768 units
        int a = u >> 6, seg = u & 63;
        const float* p = W1 + (size_t)a * (DIN + DSRC) + DIN + seg * 8;
        float4 v0 = *(const float4*)p;
        float4 v1 = *(const float4*)(p + 4);
        *(uint4*)((char*)g_Bf16 + ((size_t)a * 512 + seg * 8) * 2) = cvt8_f16(v0, v1);
    } else {
        // zero the ctx region of out (32 blocks x 256 threads x 4 = 32768)
        int u = (bx - PRE_A_BLOCKS - PRE_Q_BLOCKS - PRE_B_BLOCKS) * 256 + tid;
        ((float4*)out)[u] = make_float4(0.f, 0.f, 0.f, 0.f);
    }
}

// ---------------------------------------------------------------------------
// Main fp16 HMMA kernel. CTA: M=128 x N=128, K=512 (8 x k64), 256 threads;
// 8 warps m64 x n32; 2 CTAs/SM; 3-stage cp.async pipeline.
// ---------------------------------------------------------------------------
#define BUF_A 0
#define BUF_B 16384
#define STAGE_SZ 32768
#define S_W2   98304
#define S_RED  (S_W2 + 512)
#define SMEM_TOTAL (S_RED + 2048)         // 100864

__device__ __forceinline__ void issue_stage(uint32_t sb, int t0, int n0, int kc,
                                            int stage, int tid) {
    const uint32_t st = sb + stage * STAGE_SZ;
    #pragma unroll
    for (int i = 0; i < 4; i++) {
        const int u = tid + i * 256;
        const int r = u >> 3, s = u & 7;
        const uint32_t d = SW128((uint32_t)(r * 128 + s * 16));
        CP16(st + BUF_A + d, g_Af16 + (size_t)(t0 + r) * DSRC + kc * 64 + s * 8);
        CP16(st + BUF_B + d, g_Bf16 + (size_t)(n0 + r) * DSRC + kc * 64 + s * 8);
    }
    CP_COMMIT();
}

__global__ __launch_bounds__(256, 2) void k_main(const float* __restrict__ W2) {
    extern __shared__ __align__(16) char smem[];
    const uint32_t sb = smem_u32(smem);
    const int tid = threadIdx.x;
    const int lane = tid & 31;
    const int wid = tid >> 5;
    const int warp_m = wid & 1;          // 2 x m64
    const int warp_n = wid >> 1;         // 4 x n32
    const int n0 = blockIdx.x * 128;
    const int t0 = blockIdx.y * 128;

    float acc[4][4][4];
    #pragma unroll
    for (int mt = 0; mt < 4; mt++)
        #pragma unroll
        for (int nt = 0; nt < 4; nt++)
            #pragma unroll
            for (int c = 0; c < 4; c++) acc[mt][nt][c] = 0.f;

    if (tid < 128) ((float*)(smem + S_W2))[tid] = W2[n0 + tid];

    issue_stage(sb, t0, n0, 0, 0, tid);
    issue_stage(sb, t0, n0, 1, 1, tid);

    const uint32_t a_row = warp_m * 64 + (lane & 15);
    const uint32_t a_kadd = (lane >> 4) * 16;
    const uint32_t b_row = warp_n * 32 + (lane & 7) + ((lane >> 4) & 1) * 8;
    const uint32_t b_kadd = ((lane >> 3) & 1) * 16;

    for (int kc = 0; kc < 8; kc++) {
        if (kc == 7) CP_WAIT0(); else CP_WAIT1();
        __syncthreads();
        if (kc + 2 < 8) issue_stage(sb, t0, n0, kc + 2, (kc + 2) % 3, tid);

        const uint32_t st = sb + (kc % 3) * STAGE_SZ;
        #pragma unroll
        for (int ks = 0; ks < 4; ks++) {
            const uint32_t koff = ks * 32;
            uint32_t a[4][4];
            #pragma unroll
            for (int mt = 0; mt < 4; mt++) {
                uint32_t off = (a_row + mt * 16) * 128 + koff + a_kadd;
                ldsm4(a[mt], st + BUF_A + SW128(off));
            }
            #pragma unroll
            for (int np = 0; np < 2; np++) {
                uint32_t off = (b_row + np * 16) * 128 + koff + b_kadd;
                uint32_t b[4];
                ldsm4(b, st + BUF_B + SW128(off));
                #pragma unroll
                for (int mt = 0; mt < 4; mt++) {
                    mma_f16(acc[mt][np * 2 + 0], a[mt], b[0], b[1]);
                    mma_f16(acc[mt][np * 2 + 1], a[mt], b[2], b[3]);
                }
            }
        }
    }
    __syncthreads();

    float* qs = (float*)smem;
    #pragma unroll
    for (int i = 0; i < 8; i++) {
        int unit = tid + i * 256;
        int b = unit >> 5, c4 = unit & 31;
        float4 v = *(const float4*)(g_q + b * DAL + n0 + c4 * 4);
        float* d = qs + b * 132 + c4 * 4;
        d[0] = v.x; d[1] = v.y; d[2] = v.z; d[3] = v.w;
    }
    __syncthreads();

    {
        const float* w2s = (const float*)(smem + S_W2);
        float* red = (float*)(smem + S_RED);
        float p[4][2];
        #pragma unroll
        for (int mt = 0; mt < 4; mt++) { p[mt][0] = 0.f; p[mt][1] = 0.f; }
        const int colq = 2 * (lane & 3);
        #pragma unroll
        for (int mt = 0; mt < 4; mt++) {
            #pragma unroll
            for (int nt = 0; nt < 4; nt++) {
                int nloc = warp_n * 32 + nt * 8 + colq;
                float w2a = w2s[nloc], w2b = w2s[nloc + 1];
                #pragma unroll
                for (int h = 0; h < 2; h++) {
                    int rowloc = warp_m * 64 + mt * 16 + h * 8 + (lane >> 2);
                    int b = rowloc & 63;
                    float q0 = qs[b * 132 + nloc];
                    float q1 = qs[b * 132 + nloc + 1];
                    p[mt][h] += w2a * fast_tanh(acc[mt][nt][h * 2 + 0] + q0)
                              + w2b * fast_tanh(acc[mt][nt][h * 2 + 1] + q1);
                }
            }
        }
        #pragma unroll
        for (int mt = 0; mt < 4; mt++)
            #pragma unroll
            for (int h = 0; h < 2; h++) {
                p[mt][h] += __shfl_xor_sync(0xFFFFFFFFu, p[mt][h], 1);
                p[mt][h] += __shfl_xor_sync(0xFFFFFFFFu, p[mt][h], 2);
            }
        if ((lane & 3) == 0) {
            #pragma unroll
            for (int mt = 0; mt < 4; mt++)
                #pragma unroll
                for (int h = 0; h < 2; h++) {
                    int rowloc = warp_m * 64 + mt * 16 + h * 8 + (lane >> 2);
                    red[rowloc * 4 + warp_n] = p[mt][h];
                }
        }
        __syncthreads();
        if (tid < 128) {
            int t = t0 + tid;
            g_part[blockIdx.x * NTOK + (t & 63) * SLEN + (t >> 6)] =
                red[tid * 4] + red[tid * 4 + 1] + red[tid * 4 + 2] + red[tid * 4 + 3];
        }
    }
}

// ---------------------------------------------------------------------------
// Softmax over S per batch. Register-cached: partials read ONCE. __expf.
// ---------------------------------------------------------------------------
__global__ __launch_bounds__(256) void k_softmax(const unsigned char* __restrict__ mask,
                                                 float* __restrict__ out) {
    const int b = blockIdx.x;
    const int tid = threadIdx.x;
    __shared__ float red[256];
    const float* p0 = g_part + 0 * NTOK + b * SLEN;
    const float* p1 = g_part + 1 * NTOK + b * SLEN;
    const float* p2 = g_part + 2 * NTOK + b * SLEN;
    const float* p3 = g_part + 3 * NTOK + b * SLEN;

    float v[8];
    float lmax = -INFINITY;
    #pragma unroll
    for (int i = 0; i < 8; i++) {
        int s = tid + i * 256;
        float x = mask[s * BATCH + b] ? -INFINITY : (p0[s] + p1[s] + p2[s] + p3[s]);
        v[i] = x;
        lmax = fmaxf(lmax, x);
    }
    red[tid] = lmax; __syncthreads();
    for (int o = 128; o; o >>= 1) {
        if (tid < o) red[tid] = fmaxf(red[tid], red[tid + o]);
        __syncthreads();
    }
    float m = red[0]; __syncthreads();

    float e[8];
    float lsum = 0.f;
    #pragma unroll
    for (int i = 0; i < 8; i++) {
        e[i] = __expf(v[i] - m);
        lsum += e[i];
    }
    red[tid] = lsum; __syncthreads();
    for (int o = 128; o; o >>= 1) {
        if (tid < o) red[tid] += red[tid + o];
        __syncthreads();
    }
    float inv = 1.f / red[0];

    #pragma unroll
    for (int i = 0; i < 8; i++) {
        int s = tid + i * 256;
        out[CTX_ELEMS + s * BATCH + b] = e[i] * inv;
    }
}

// ---------------------------------------------------------------------------
// ctx[b, d] = sum_s attn[s, b] * fp16src[s, b, d]
// grid (64, 16) = 1024 CTAs; 128 s per CTA.
// Thread owns an 8-wide d granule (one 16B load per s); 64 threads/row,
// 4 rows in flight; s-unroll x4 -> 64B outstanding per thread.
// ---------------------------------------------------------------------------
#define CTX_CHUNKS 16
__global__ __launch_bounds__(256) void k_ctx(float* __restrict__ out) {
    const int b = blockIdx.x;
    const int c = blockIdx.y;
    const int tid = threadIdx.x;
    const int dg = tid & 63;              // d granule: 8 halves
    const int sr = tid >> 6;              // 0..3 row group
    const float* attn = out + CTX_ELEMS;

    float acc[8];
    #pragma unroll
    for (int i = 0; i < 8; i++) acc[i] = 0.f;

    const int s0 = c * (SLEN / CTX_CHUNKS) + sr;
    #pragma unroll 1
    for (int s = s0; s < c * (SLEN / CTX_CHUNKS) + SLEN / CTX_CHUNKS; s += 16) {
        #pragma unroll
        for (int j = 0; j < 4; j++) {
            int ss = s + j * 4;
            float a = attn[ss * BATCH + b];
            uint4 raw = *(const uint4*)(g_Af16 + (size_t)(ss * BATCH + b) * DSRC + dg * 8);
            const __half2* h = (const __half2*)&raw;
            #pragma unroll
            for (int k = 0; k < 4; k++) {
                float2 f = __half22float2(h[k]);
                acc[k * 2 + 0] += a * f.x;
                acc[k * 2 + 1] += a * f.y;
            }
        }
    }
    #pragma unroll
    for (int i = 0; i < 8; i++)
        atomicAdd(&out[b * DSRC + dg * 8 + i], acc[i]);
}

// ---------------------------------------------------------------------------
extern "C" void kernel_launch(void* const* d_in, const int* in_sizes, int n_in,
                              void* d_out, int out_size) {
    const float* inp = (const float*)d_in[0];
    const float* src = (const float*)d_in[1];
    const unsigned char* mask = (const unsigned char*)d_in[2];
    const float* W1 = (const float*)d_in[3];
    const float* b1 = (const float*)d_in[4];
    const float* W2 = (const float*)d_in[5];
    float* out = (float*)d_out;

    cudaFuncSetAttribute(k_main, cudaFuncAttributeMaxDynamicSharedMemorySize, SMEM_TOTAL);

    k_pre<<<PRE_TOTAL, 256>>>(src, inp, W1, b1, out);

    dim3 gg(4, NTOK / 128);               // n-tile fast, token-tile slow
    k_main<<<gg, 256, SMEM_TOTAL>>>(W2);

    k_softmax<<<BATCH, 256>>>(mask, out);
    k_ctx<<<dim3(BATCH, CTX_CHUNKS), 256>>>(out);
}